// round 2
// baseline (speedup 1.0000x reference)
#include <cuda_runtime.h>

#define BATCH 4
#define SEQ   2048
#define DMODEL 256
#define NHEAD 4
#define HDIM  64
#define BHTOT (BATCH*NHEAD)   // 16

// Scratch: Q and K stored transposed [bh][d][s] for conflict-free attention tiles.
// V stored natural [bh][s][d].
__device__ float g_Qt[BHTOT * HDIM * SEQ];   // 2,097,152 floats (8 MB)
__device__ float g_Kt[BHTOT * HDIM * SEQ];
__device__ float g_V [BHTOT * SEQ * HDIM];

// ---------------------------------------------------------------------------
// Kernel 1: fused QKV projection.  qkv[m,e] = sum_d x[m,d]*W[e,d] + b[e]
// M = B*S = 8192, N = 768, K = 256.  Tile 128x64, 256 threads, 8x4 micro-tile.
// Epilogue scatters into g_Qt/g_Kt (transposed) and g_V (natural).
// ---------------------------------------------------------------------------
__global__ __launch_bounds__(256)
void qkv_gemm_kernel(const float* __restrict__ x,
                     const float* __restrict__ W,
                     const float* __restrict__ bias)
{
    __shared__ float Xs[128][32];       // x tile, natural (row accesses are ty-broadcast)
    __shared__ float Ws[64][33];        // W tile, padded (col accesses stride 33 -> 2-way max)

    const int tid = threadIdx.x;
    const int tx = tid & 15;            // 0..15 -> 4 output cols
    const int ty = tid >> 4;            // 0..15 -> 8 output rows
    const int m0 = blockIdx.y * 128;
    const int n0 = blockIdx.x * 64;

    float acc[8][4];
#pragma unroll
    for (int i = 0; i < 8; i++)
#pragma unroll
        for (int j = 0; j < 4; j++) acc[i][j] = 0.f;

    for (int k0 = 0; k0 < DMODEL; k0 += 32) {
        // load X tile: 128x32 floats = 1024 float4, 4 per thread (coalesced)
#pragma unroll
        for (int e = 0; e < 4; e++) {
            int f  = tid + e * 256;
            int m  = f >> 3;            // 8 float4 per row
            int k4 = (f & 7) << 2;
            float4 v = *(const float4*)&x[(m0 + m) * DMODEL + k0 + k4];
            *(float4*)&Xs[m][k4] = v;
        }
        // load W tile: 64x32 floats = 512 float4, 2 per thread; scalar stores into padded smem
#pragma unroll
        for (int e = 0; e < 2; e++) {
            int f  = tid + e * 256;
            int n  = f >> 3;
            int k4 = (f & 7) << 2;
            float4 v = *(const float4*)&W[(n0 + n) * DMODEL + k0 + k4];
            Ws[n][k4 + 0] = v.x; Ws[n][k4 + 1] = v.y;
            Ws[n][k4 + 2] = v.z; Ws[n][k4 + 3] = v.w;
        }
        __syncthreads();

#pragma unroll
        for (int kk = 0; kk < 32; kk++) {
            float a[8], b[4];
#pragma unroll
            for (int i = 0; i < 8; i++) a[i] = Xs[ty * 8 + i][kk];
#pragma unroll
            for (int j = 0; j < 4; j++) b[j] = Ws[tx * 4 + j][kk];
#pragma unroll
            for (int i = 0; i < 8; i++)
#pragma unroll
                for (int j = 0; j < 4; j++)
                    acc[i][j] += a[i] * b[j];
        }
        __syncthreads();
    }

    // epilogue: bias + scatter into head-split layouts
    float bj[4];
#pragma unroll
    for (int j = 0; j < 4; j++) bj[j] = bias[n0 + tx * 4 + j];

#pragma unroll
    for (int i = 0; i < 8; i++) {
        int m = m0 + ty * 8 + i;
        int b_idx = m >> 11;            // / SEQ
        int s     = m & (SEQ - 1);
#pragma unroll
        for (int j = 0; j < 4; j++) {
            int e = n0 + tx * 4 + j;
            float v = acc[i][j] + bj[j];
            int which = e >> 8;         // 0=Q 1=K 2=V
            int rem   = e & 255;
            int h     = rem >> 6;
            int dh    = rem & 63;
            int bh    = b_idx * NHEAD + h;
            if (which == 0)
                g_Qt[(bh * HDIM + dh) * SEQ + s] = v;
            else if (which == 1)
                g_Kt[(bh * HDIM + dh) * SEQ + s] = v;
            else
                g_V[(bh * SEQ + s) * HDIM + dh] = v;
        }
    }
}

// ---------------------------------------------------------------------------
// Kernel 2: flash attention, fp32.
// Block: 128 query rows (BM) x full head, loops 32 key tiles of 64 (BN).
// 256 threads, thread (ty,tx) owns 8 rows x 4 output dims.
// smem (dynamic, 96 KB): Qts[64][128], Kts[64][64], Vs[64][64], Ps[128][64].
// All smem accesses are LDS.128/STS.128 conflict-free (rows indexed by d/k,
// cols by r/c; row-index only varies with ty -> 2 addrs per warp = broadcast).
// ---------------------------------------------------------------------------
__global__ __launch_bounds__(256)
void attn_kernel(float* __restrict__ out)
{
    extern __shared__ float sm[];
    float* Qts = sm;                    // [64][128]
    float* Kts = Qts + 64 * 128;        // [64][64]
    float* Vs  = Kts + 64 * 64;         // [64][64]
    float* Ps  = Vs  + 64 * 64;         // [128][64]

    const int tid = threadIdx.x;
    const int tx = tid & 15;
    const int ty = tid >> 4;
    const int bh = blockIdx.y;
    const int q0 = blockIdx.x * 128;

    const float* Qtg = g_Qt + bh * HDIM * SEQ;
    const float* Ktg = g_Kt + bh * HDIM * SEQ;
    const float* Vg  = g_V  + bh * SEQ * HDIM;

    // load Q tile: Qts[d][r] = Qtg[d*SEQ + q0 + r]  (64*128 = 2048 float4)
#pragma unroll
    for (int e = 0; e < 8; e++) {
        int f  = tid + e * 256;
        int d  = f >> 5;                // 32 float4 per 128-wide row
        int r4 = (f & 31) << 2;
        *(float4*)&Qts[d * 128 + r4] = *(const float4*)&Qtg[d * SEQ + q0 + r4];
    }

    float m_i[8], l_i[8], o[8][4];
#pragma unroll
    for (int i = 0; i < 8; i++) {
        m_i[i] = -1e30f; l_i[i] = 0.f;
#pragma unroll
        for (int j = 0; j < 4; j++) o[i][j] = 0.f;
    }

    for (int k0 = 0; k0 < SEQ; k0 += 64) {
        __syncthreads();   // previous iteration's readers of Kts/Vs done

        // K tile: Kts[d][c] = Ktg[d*SEQ + k0 + c]   (64*64 = 1024 float4)
#pragma unroll
        for (int e = 0; e < 4; e++) {
            int f  = tid + e * 256;
            int d  = f >> 4;
            int c4 = (f & 15) << 2;
            *(float4*)&Kts[d * 64 + c4] = *(const float4*)&Ktg[d * SEQ + k0 + c4];
        }
        // V tile: natural, contiguous copy
#pragma unroll
        for (int e = 0; e < 4; e++) {
            int f = tid + e * 256;
            *(float4*)&Vs[f * 4] = *(const float4*)&Vg[k0 * HDIM + f * 4];
        }
        __syncthreads();

        // S = Q K^T (8x4 per thread): rows ty*8.., cols tx*4..
        float s[8][4];
#pragma unroll
        for (int i = 0; i < 8; i++)
#pragma unroll
            for (int j = 0; j < 4; j++) s[i][j] = 0.f;

#pragma unroll 8
        for (int d = 0; d < 64; d++) {
            float4 qa = *(const float4*)&Qts[d * 128 + ty * 8];
            float4 qb = *(const float4*)&Qts[d * 128 + ty * 8 + 4];
            float4 kv = *(const float4*)&Kts[d * 64 + tx * 4];
            float qq[8] = {qa.x, qa.y, qa.z, qa.w, qb.x, qb.y, qb.z, qb.w};
            float kk[4] = {kv.x, kv.y, kv.z, kv.w};
#pragma unroll
            for (int i = 0; i < 8; i++)
#pragma unroll
                for (int j = 0; j < 4; j++)
                    s[i][j] += qq[i] * kk[j];
        }

        // online softmax (scale 1/sqrt(64) = 0.125)
#pragma unroll
        for (int i = 0; i < 8; i++) {
#pragma unroll
            for (int j = 0; j < 4; j++) s[i][j] *= 0.125f;
            float tm = fmaxf(fmaxf(s[i][0], s[i][1]), fmaxf(s[i][2], s[i][3]));
#pragma unroll
            for (int off = 8; off > 0; off >>= 1)
                tm = fmaxf(tm, __shfl_xor_sync(0xffffffffu, tm, off, 16));
            float nm = fmaxf(m_i[i], tm);
            float alpha = __expf(m_i[i] - nm);
            m_i[i] = nm;
            float rs = 0.f;
#pragma unroll
            for (int j = 0; j < 4; j++) { s[i][j] = __expf(s[i][j] - nm); rs += s[i][j]; }
#pragma unroll
            for (int off = 8; off > 0; off >>= 1)
                rs += __shfl_xor_sync(0xffffffffu, rs, off, 16);
            l_i[i] = l_i[i] * alpha + rs;
#pragma unroll
            for (int j = 0; j < 4; j++) o[i][j] *= alpha;
        }

        // P -> smem (STS.128, conflict-free)
#pragma unroll
        for (int i = 0; i < 8; i++) {
            float4 pv = make_float4(s[i][0], s[i][1], s[i][2], s[i][3]);
            *(float4*)&Ps[(ty * 8 + i) * 64 + tx * 4] = pv;
        }
        __syncthreads();

        // O += P @ V  (k chunks of 4)
#pragma unroll 4
        for (int k4 = 0; k4 < 64; k4 += 4) {
            float4 v0 = *(const float4*)&Vs[(k4 + 0) * 64 + tx * 4];
            float4 v1 = *(const float4*)&Vs[(k4 + 1) * 64 + tx * 4];
            float4 v2 = *(const float4*)&Vs[(k4 + 2) * 64 + tx * 4];
            float4 v3 = *(const float4*)&Vs[(k4 + 3) * 64 + tx * 4];
#pragma unroll
            for (int i = 0; i < 8; i++) {
                float4 p = *(const float4*)&Ps[(ty * 8 + i) * 64 + k4];
                o[i][0] += p.x * v0.x + p.y * v1.x + p.z * v2.x + p.w * v3.x;
                o[i][1] += p.x * v0.y + p.y * v1.y + p.z * v2.y + p.w * v3.y;
                o[i][2] += p.x * v0.z + p.y * v1.z + p.z * v2.z + p.w * v3.z;
                o[i][3] += p.x * v0.w + p.y * v1.w + p.z * v2.w + p.w * v3.w;
            }
        }
    }

    // epilogue: out[bh][q][d] = o / l
#pragma unroll
    for (int i = 0; i < 8; i++) {
        float inv = 1.f / l_i[i];
        int r = q0 + ty * 8 + i;
#pragma unroll
        for (int j = 0; j < 4; j++)
            out[(bh * SEQ + r) * HDIM + tx * 4 + j] = o[i][j] * inv;
    }
}

// ---------------------------------------------------------------------------
extern "C" void kernel_launch(void* const* d_in, const int* in_sizes, int n_in,
                              void* d_out, int out_size)
{
    const float* x    = (const float*)d_in[0];
    const float* W    = (const float*)d_in[1];
    const float* bias = (const float*)d_in[2];
    float* out        = (float*)d_out;

    const int smem = (64 * 128 + 64 * 64 + 64 * 64 + 128 * 64) * sizeof(float); // 98304
    cudaFuncSetAttribute(attn_kernel, cudaFuncAttributeMaxDynamicSharedMemorySize, smem);

    qkv_gemm_kernel<<<dim3(768 / 64, 8192 / 128), 256>>>(x, W, bias);
    attn_kernel<<<dim3(SEQ / 128, BHTOT), 256, smem>>>(out);
}